// round 1
// baseline (speedup 1.0000x reference)
#include <cuda_runtime.h>

// NCDE decoder: B=4096, L=256 (255 RK4 steps), C=16, H=128, O=4.
// One block (128 threads) per batch element; thread = hidden index h.
// Per-thread registers hold W2[0][h,:], W2[1][h,:], b2[h,:] (48 floats).
// uz = z@W1 tracked incrementally (exact, since update is linear in z).

#define Hh 128
#define Cc 16
#define Ll 256
#define NSTEP 255

__device__ __forceinline__ float tanh_ex2(float x) {
    // tanh(x) = 1 - 2/(e^{2x}+1); e^{2x} = 2^{x * 2*log2(e)}
    // Large +x: ex2 -> inf, rcp(inf+1)=0 -> 1.  Large -x: ex2->0, rcp(1)=1 -> -1.
    float e, r;
    asm("ex2.approx.f32 %0, %1;" : "=f"(e) : "f"(x * 2.8853900817779268f));
    asm("rcp.approx.f32 %0, %1;" : "=f"(r) : "f"(e + 1.0f));
    return fmaf(-2.0f, r, 1.0f);
}

__device__ __forceinline__ void redsum2(float& a, float& b) {
#pragma unroll
    for (int off = 16; off; off >>= 1) {
        a += __shfl_xor_sync(0xffffffffu, a, off);
        b += __shfl_xor_sync(0xffffffffu, b, off);
    }
}

__device__ __forceinline__ void redsum4(float& a, float& b, float& c, float& d) {
#pragma unroll
    for (int off = 16; off; off >>= 1) {
        a += __shfl_xor_sync(0xffffffffu, a, off);
        b += __shfl_xor_sync(0xffffffffu, b, off);
        c += __shfl_xor_sync(0xffffffffu, c, off);
        d += __shfl_xor_sync(0xffffffffu, d, off);
    }
}

__global__ __launch_bounds__(128) void ncde_kernel(
    const float* __restrict__ coeffs,   // (B, 255, 64)
    const float* __restrict__ W_init,   // (16, 128)
    const float* __restrict__ b_init,   // (128)
    const float* __restrict__ W1,       // (128, 2)
    const float* __restrict__ b1,       // (2)
    const float* __restrict__ W2,       // (2, 2048)
    const float* __restrict__ b2,       // (2048)
    const float* __restrict__ W_out,    // (128, 4)
    const float* __restrict__ b_out,    // (4)
    float* __restrict__ out)            // (B, 256, 4)
{
    const int b   = blockIdx.x;
    const int h   = threadIdx.x;
    const int lane = h & 31;
    const int warp = h >> 5;

    __shared__ float sxd[3][Cc];    // xd0, xdh, xd1 for current step
    __shared__ float sred[2][8];    // double-buffered 2-value block reduction
    __shared__ float sredo[16];     // 4-value output reduction
    __shared__ float sa0[Cc];

    // ---- per-thread weight slices (registers) ----
    float w2a[Cc], w2b[Cc], b2r[Cc];
#pragma unroll
    for (int c = 0; c < Cc; c++) {
        w2a[c] = W2[h * Cc + c];
        w2b[c] = W2[Hh * Cc + h * Cc + c];   // W2 row 1 at offset 2048
        b2r[c] = b2[h * Cc + c];
    }
    const float w1a = W1[h * 2 + 0];
    const float w1b = W1[h * 2 + 1];
    const float wo0 = W_out[h * 4 + 0];
    const float wo1 = W_out[h * 4 + 1];
    const float wo2 = W_out[h * 4 + 2];
    const float wo3 = W_out[h * 4 + 3];
    const float b10 = b1[0];
    const float b11 = b1[1];
    const float bout = (h < 4) ? b_out[h] : 0.0f;

    const float* crow = coeffs + (size_t)b * (NSTEP * 64);

    // ---- init: z0 = X0 @ W_init + b_init ----
    if (h < Cc) sa0[h] = crow[h];          // a[:,0,:]
    __syncthreads();

    float z = b_init[h];
#pragma unroll
    for (int c = 0; c < Cc; c++) z = fmaf(sa0[c], W_init[c * Hh + h], z);

    // prefetch step-0 coefficient segments into registers
    float pb = 0.f, pc = 0.f, pd = 0.f;
    if (h < Cc) { pb = crow[16 + h]; pc = crow[32 + h]; pd = crow[48 + h]; }

    // uz = z @ W1 (2 scalars, block reduction)
    float uz0 = z * w1a, uz1 = z * w1b;
    redsum2(uz0, uz1);
    if (lane == 0) { sred[0][warp * 2] = uz0; sred[0][warp * 2 + 1] = uz1; }
    __syncthreads();
    uz0 = sred[0][0] + sred[0][2] + sred[0][4] + sred[0][6];
    uz1 = sred[0][1] + sred[0][3] + sred[0][5] + sred[0][7];

    // output t = 0
    {
        float p0 = z * wo0, p1 = z * wo1, p2 = z * wo2, p3 = z * wo3;
        redsum4(p0, p1, p2, p3);
        if (lane == 0) {
            sredo[warp * 4 + 0] = p0; sredo[warp * 4 + 1] = p1;
            sredo[warp * 4 + 2] = p2; sredo[warp * 4 + 3] = p3;
        }
        __syncthreads();
        if (h < 4)
            out[(size_t)b * (Ll * 4) + h] =
                sredo[h] + sredo[4 + h] + sredo[8 + h] + sredo[12 + h] + bout;
    }

    int ph = 1;
    for (int t = 0; t < NSTEP; t++) {
        __syncthreads();   // sxd / sredo reuse guard
        if (h < Cc) {
            sxd[0][h] = pb;
            sxd[1][h] = fmaf(0.25f, pd, fmaf(0.5f, pc, pb));
            sxd[2][h] = pb + pc + pd;
        }
        __syncthreads();
        if (h < Cc && (t + 1) < NSTEP) {   // prefetch next step's row
            const float* r2 = crow + (size_t)(t + 1) * 64;
            pb = r2[16 + h]; pc = r2[32 + h]; pd = r2[48 + h];
        }

        float uk0 = 0.f, uk1 = 0.f;     // previous stage's k @ W1
        float s0 = 0.f, s1 = 0.f;       // weighted sum of uk's
        float ksum = 0.f;               // k1 + 2k2 + 2k3 + k4  (per h)

#pragma unroll
        for (int st = 0; st < 4; st++) {
            const float alpha = (st == 0) ? 0.f : (st == 3) ? 1.f : 0.5f;
            const int   xi    = (st == 0) ? 0   : (st == 3) ? 2   : 1;
            const float wgt   = (st == 0 || st == 3) ? 1.f : 2.f;

            const float u0 = fmaf(alpha, uk0, uz0) + b10;
            const float u1 = fmaf(alpha, uk1, uz1) + b11;
            const float h0 = fmaxf(u0, 0.f);
            const float h1 = fmaxf(u1, 0.f);

            float ka = 0.f, kb = 0.f;   // two accumulators for ILP
#pragma unroll
            for (int c = 0; c < Cc; c += 2) {
                float a0 = fmaf(h0, w2a[c],     fmaf(h1, w2b[c],     b2r[c]));
                float a1 = fmaf(h0, w2a[c + 1], fmaf(h1, w2b[c + 1], b2r[c + 1]));
                ka = fmaf(tanh_ex2(a0), sxd[xi][c],     ka);
                kb = fmaf(tanh_ex2(a1), sxd[xi][c + 1], kb);
            }
            const float k = ka + kb;
            ksum = fmaf(wgt, k, ksum);

            float p0 = k * w1a, p1 = k * w1b;
            redsum2(p0, p1);
            if (lane == 0) { sred[ph][warp * 2] = p0; sred[ph][warp * 2 + 1] = p1; }
            __syncthreads();
            uk0 = sred[ph][0] + sred[ph][2] + sred[ph][4] + sred[ph][6];
            uk1 = sred[ph][1] + sred[ph][3] + sred[ph][5] + sred[ph][7];
            s0 = fmaf(wgt, uk0, s0);
            s1 = fmaf(wgt, uk1, s1);
            ph ^= 1;
        }

        z   = fmaf(ksum, 1.f / 6.f, z);
        uz0 = fmaf(s0,   1.f / 6.f, uz0);
        uz1 = fmaf(s1,   1.f / 6.f, uz1);

        // output t+1
        float p0 = z * wo0, p1 = z * wo1, p2 = z * wo2, p3 = z * wo3;
        redsum4(p0, p1, p2, p3);
        if (lane == 0) {
            sredo[warp * 4 + 0] = p0; sredo[warp * 4 + 1] = p1;
            sredo[warp * 4 + 2] = p2; sredo[warp * 4 + 3] = p3;
        }
        __syncthreads();
        if (h < 4)
            out[(size_t)b * (Ll * 4) + (size_t)(t + 1) * 4 + h] =
                sredo[h] + sredo[4 + h] + sredo[8 + h] + sredo[12 + h] + bout;
    }
}

extern "C" void kernel_launch(void* const* d_in, const int* in_sizes, int n_in,
                              void* d_out, int out_size) {
    const float* coeffs = (const float*)d_in[0];
    const float* W_init = (const float*)d_in[1];
    const float* b_init = (const float*)d_in[2];
    const float* W1     = (const float*)d_in[3];
    const float* b1     = (const float*)d_in[4];
    const float* W2     = (const float*)d_in[5];
    const float* b2     = (const float*)d_in[6];
    const float* W_out  = (const float*)d_in[7];
    const float* b_out  = (const float*)d_in[8];
    float* out = (float*)d_out;

    ncde_kernel<<<4096, 128>>>(coeffs, W_init, b_init, W1, b1, W2, b2,
                               W_out, b_out, out);
}

// round 3
// speedup vs baseline: 1.0797x; 1.0797x over previous
#include <cuda_runtime.h>

// NCDE decoder: B=4096, 255 RK4 steps, C=16, H=128, O=4.
// One 128-thread block per batch element; thread = hidden index h.
// MUFU reduction: one rcp per 4 tanh (quad-reciprocal trick).
// FMA reduction: fma.rn.f32x2 packed args; shfl-butterfly reductions
// (redux.sync.add.f32 does NOT exist on sm_103).

#define Hh 128
#define Cc 16
#define NSTEP 255
#define L2E2 2.8853900817779268f   // 2*log2(e), folded into W2/b2

typedef unsigned long long ull;

__device__ __forceinline__ ull pack2(float lo, float hi) {
    ull r; asm("mov.b64 %0, {%1, %2};" : "=l"(r) : "f"(lo), "f"(hi)); return r;
}
__device__ __forceinline__ void unpack2(ull v, float& lo, float& hi) {
    asm("mov.b64 {%0, %1}, %2;" : "=f"(lo), "=f"(hi) : "l"(v));
}
__device__ __forceinline__ ull fma2(ull a, ull b, ull c) {
    ull d; asm("fma.rn.f32x2 %0, %1, %2, %3;" : "=l"(d) : "l"(a), "l"(b), "l"(c)); return d;
}
__device__ __forceinline__ float ex2f(float x) {
    float e; asm("ex2.approx.f32 %0, %1;" : "=f"(e) : "f"(x)); return e;
}
__device__ __forceinline__ float rcpf(float x) {
    float r; asm("rcp.approx.f32 %0, %1;" : "=f"(r) : "f"(x)); return r;
}

__device__ __forceinline__ void redsum2(float& a, float& b) {
#pragma unroll
    for (int off = 16; off; off >>= 1) {
        a += __shfl_xor_sync(0xffffffffu, a, off);
        b += __shfl_xor_sync(0xffffffffu, b, off);
    }
}

__device__ __forceinline__ void redsum4(float& a, float& b, float& c, float& d) {
#pragma unroll
    for (int off = 16; off; off >>= 1) {
        a += __shfl_xor_sync(0xffffffffu, a, off);
        b += __shfl_xor_sync(0xffffffffu, b, off);
        c += __shfl_xor_sync(0xffffffffu, c, off);
        d += __shfl_xor_sync(0xffffffffu, d, off);
    }
}

__global__ __launch_bounds__(128) void ncde_kernel(
    const float* __restrict__ coeffs,   // (B, 255, 64)
    const float* __restrict__ W_init,   // (16, 128)
    const float* __restrict__ b_init,   // (128)
    const float* __restrict__ W1,       // (128, 2)
    const float* __restrict__ b1,       // (2)
    const float* __restrict__ W2,       // (2, 2048)
    const float* __restrict__ b2,       // (2048)
    const float* __restrict__ W_out,    // (128, 4)
    const float* __restrict__ b_out,    // (4)
    float* __restrict__ out)            // (B, 256, 4)
{
    const int b    = blockIdx.x;
    const int h    = threadIdx.x;
    const int lane = h & 31;
    const int warp = h >> 5;

    __shared__ __align__(16) float sxd2[3][Cc];  // -2*xdot per stage-class
    __shared__ float ssum[3];                    // sum_c xdot_c per stage-class
    __shared__ float sred[2][8];                 // double-buffered uk reduction
    __shared__ float sredo[16];                  // output reduction
    __shared__ float sa0[Cc];

    // ---- per-thread packed weight slices (arg scale 2*log2e pre-folded) ----
    ull wa[8], wbp[8], b2p[8];
#pragma unroll
    for (int p = 0; p < 8; p++) {
        wa[p]  = pack2(W2[h * Cc + 2 * p] * L2E2,           W2[h * Cc + 2 * p + 1] * L2E2);
        wbp[p] = pack2(W2[Hh * Cc + h * Cc + 2 * p] * L2E2, W2[Hh * Cc + h * Cc + 2 * p + 1] * L2E2);
        b2p[p] = pack2(b2[h * Cc + 2 * p] * L2E2,           b2[h * Cc + 2 * p + 1] * L2E2);
    }
    const float w1a = W1[h * 2 + 0], w1b = W1[h * 2 + 1];
    const float wo0 = W_out[h * 4 + 0], wo1 = W_out[h * 4 + 1];
    const float wo2 = W_out[h * 4 + 2], wo3 = W_out[h * 4 + 3];
    const float b10 = b1[0], b11 = b1[1];
    const float bout = (h < 4) ? b_out[h] : 0.0f;

    const float* crow = coeffs + (size_t)b * (NSTEP * 64);

    float pb = 0.f, pc = 0.f, pd = 0.f;
    if (h < Cc) { sa0[h] = crow[h]; pb = crow[16 + h]; pc = crow[32 + h]; pd = crow[48 + h]; }

    // SW1 = column sums of W1 (for k = S + q decomposition)
    {
        float r0 = w1a, r1 = w1b;
        redsum2(r0, r1);
        if (lane == 0) { sred[0][warp * 2] = r0; sred[0][warp * 2 + 1] = r1; }
    }
    __syncthreads();
    const float SW1a = sred[0][0] + sred[0][2] + sred[0][4] + sred[0][6];
    const float SW1b = sred[0][1] + sred[0][3] + sred[0][5] + sred[0][7];

    // z0 = X0 @ W_init + b_init
    float z = b_init[h];
#pragma unroll
    for (int c = 0; c < Cc; c++) z = fmaf(sa0[c], W_init[c * Hh + h], z);

    // uz = z @ W1 ; output t=0
    float uz0, uz1;
    {
        float r0 = z * w1a, r1 = z * w1b;
        redsum2(r0, r1);
        if (lane == 0) { sred[1][warp * 2] = r0; sred[1][warp * 2 + 1] = r1; }
        float p0 = z * wo0, p1 = z * wo1, p2 = z * wo2, p3 = z * wo3;
        redsum4(p0, p1, p2, p3);
        if (lane == 0) {
            sredo[warp * 4 + 0] = p0; sredo[warp * 4 + 1] = p1;
            sredo[warp * 4 + 2] = p2; sredo[warp * 4 + 3] = p3;
        }
        __syncthreads();
        uz0 = sred[1][0] + sred[1][2] + sred[1][4] + sred[1][6];
        uz1 = sred[1][1] + sred[1][3] + sred[1][5] + sred[1][7];
        if (h < 4)
            out[(size_t)b * 1024 + h] =
                sredo[h] + sredo[4 + h] + sredo[8 + h] + sredo[12 + h] + bout;
    }

    int ph = 0;
    for (int t = 0; t < NSTEP; t++) {
        // stage xdot tables (threads 0..15) + their channel-sums (warp 0)
        if (h < Cc) {
            float x0 = pb;
            float xh = fmaf(0.25f, pd, fmaf(0.5f, pc, pb));
            float x1 = pb + pc + pd;
            sxd2[0][h] = -2.f * x0; sxd2[1][h] = -2.f * xh; sxd2[2][h] = -2.f * x1;
        }
        if (warp == 0) {
            float SB = pb, SC = pc, SD = pd;   // lanes >=16 hold 0
#pragma unroll
            for (int off = 1; off < 16; off <<= 1) {
                SB += __shfl_xor_sync(0xffffffffu, SB, off);
                SC += __shfl_xor_sync(0xffffffffu, SC, off);
                SD += __shfl_xor_sync(0xffffffffu, SD, off);
            }
            if (lane == 0) {
                ssum[0] = SB;
                ssum[1] = fmaf(0.25f, SD, fmaf(0.5f, SC, SB));
                ssum[2] = SB + SC + SD;
            }
        }
        __syncthreads();
        if (h < Cc && (t + 1) < NSTEP) {       // prefetch next step's coeff row
            const float* r2 = crow + (size_t)(t + 1) * 64;
            pb = r2[16 + h]; pc = r2[32 + h]; pd = r2[48 + h];
        }
        const float S0 = ssum[0], Sh_ = ssum[1], S1 = ssum[2];

        float uk0 = 0.f, uk1 = 0.f, s0 = 0.f, s1 = 0.f, ksum = 0.f;

#pragma unroll
        for (int st = 0; st < 4; st++) {
            const float alpha = (st == 0) ? 0.f : (st == 3) ? 1.f : 0.5f;
            const int   xi    = (st == 0) ? 0   : (st == 3) ? 2   : 1;
            const float wgt   = (st == 0 || st == 3) ? 1.f : 2.f;
            const float Sst   = (st == 0) ? S0 : (st == 3) ? S1 : Sh_;

            const float h0 = fmaxf(fmaf(alpha, uk0, uz0) + b10, 0.f);
            const float h1 = fmaxf(fmaf(alpha, uk1, uz1) + b11, 0.f);
            const ull H0 = pack2(h0, h0), H1 = pack2(h1, h1);

            float qa = 0.f, qb = 0.f;
#pragma unroll
            for (int qi = 0; qi < 4; qi++) {
                ull y0 = fma2(H0, wa[2 * qi],     fma2(H1, wbp[2 * qi],     b2p[2 * qi]));
                ull y1 = fma2(H0, wa[2 * qi + 1], fma2(H1, wbp[2 * qi + 1], b2p[2 * qi + 1]));
                float ya, yb, yc, yd;
                unpack2(y0, ya, yb); unpack2(y1, yc, yd);
                // t_i = e^{2a_i}+1 ; clamp keeps quad product finite
                const float t0 = ex2f(fminf(ya, 30.f)) + 1.f;
                const float t1 = ex2f(fminf(yb, 30.f)) + 1.f;
                const float t2 = ex2f(fminf(yc, 30.f)) + 1.f;
                const float t3 = ex2f(fminf(yd, 30.f)) + 1.f;
                const float4 x4 = *(const float4*)&sxd2[xi][4 * qi];
                const float P0 = t0 * t1;
                const float N0 = fmaf(x4.y, t0, x4.x * t1);
                const float P1 = t2 * t3;
                const float N1 = fmaf(x4.w, t2, x4.z * t3);
                const float R  = rcpf(P0 * P1);
                const float N  = fmaf(N1, P0, N0 * P1);
                if (qi & 1) qb = fmaf(R, N, qb); else qa = fmaf(R, N, qa);
            }
            const float q = qa + qb;            // k_h = Sst + q_h

            float r0 = q * w1a, r1 = q * w1b;
            redsum2(r0, r1);
            if (lane == 0) { sred[ph][warp * 2] = r0; sred[ph][warp * 2 + 1] = r1; }
            __syncthreads();
            const float Q0 = sred[ph][0] + sred[ph][2] + sred[ph][4] + sred[ph][6];
            const float Q1 = sred[ph][1] + sred[ph][3] + sred[ph][5] + sred[ph][7];
            uk0 = fmaf(Sst, SW1a, Q0);
            uk1 = fmaf(Sst, SW1b, Q1);
            s0 = fmaf(wgt, uk0, s0);
            s1 = fmaf(wgt, uk1, s1);
            ksum = fmaf(wgt, Sst + q, ksum);
            ph ^= 1;
        }

        z   = fmaf(ksum, 1.f / 6.f, z);
        uz0 = fmaf(s0,   1.f / 6.f, uz0);
        uz1 = fmaf(s1,   1.f / 6.f, uz1);

        // output row t+1
        float p0 = z * wo0, p1 = z * wo1, p2 = z * wo2, p3 = z * wo3;
        redsum4(p0, p1, p2, p3);
        if (lane == 0) {
            sredo[warp * 4 + 0] = p0; sredo[warp * 4 + 1] = p1;
            sredo[warp * 4 + 2] = p2; sredo[warp * 4 + 3] = p3;
        }
        __syncthreads();
        if (h < 4)
            out[(size_t)b * 1024 + (size_t)(t + 1) * 4 + h] =
                sredo[h] + sredo[4 + h] + sredo[8 + h] + sredo[12 + h] + bout;
    }
}

extern "C" void kernel_launch(void* const* d_in, const int* in_sizes, int n_in,
                              void* d_out, int out_size) {
    const float* coeffs = (const float*)d_in[0];
    const float* W_init = (const float*)d_in[1];
    const float* b_init = (const float*)d_in[2];
    const float* W1     = (const float*)d_in[3];
    const float* b1     = (const float*)d_in[4];
    const float* W2     = (const float*)d_in[5];
    const float* b2     = (const float*)d_in[6];
    const float* W_out  = (const float*)d_in[7];
    const float* b_out  = (const float*)d_in[8];
    float* out = (float*)d_out;

    ncde_kernel<<<4096, 128>>>(coeffs, W_init, b_init, W1, b1, W2, b2,
                               W_out, b_out, out);
}